// round 4
// baseline (speedup 1.0000x reference)
#include <cuda_runtime.h>

// ---------------------------------------------------------------------------
// TemporalGNN: 2x TransformerConv(heads=1), N=100k nodes, E=800k edges, C=128.
//
// CSR (by destination) built once per call, then each layer:
//   [gemm4: q,k,v,s = X@W+b] -> [fused per-node attention + skip (+relu)]
// Zero floating-point atomics. edge_index dtype (int32 vs int64) detected at
// runtime on device; all index consumption is bounds-guarded.
// ---------------------------------------------------------------------------

#define NN 100000
#define NE 800000
#define C  128
#define CHUNK 1024
#define NBLK ((NN + CHUNK - 1) / CHUNK)  // 98

__device__ float g_q[NN * C];
__device__ float g_k[NN * C];
__device__ float g_v[NN * C];
__device__ float g_s[NN * C];
__device__ float g_h[NN * C];
__device__ int   g_deg[NN];
__device__ int   g_rptmp[NN + 1];
__device__ int   g_rowptr[NN + 1];
__device__ int   g_wpos[NN];
__device__ int   g_blocksums[NBLK];
__device__ int   g_blockoffs[NBLK];
__device__ int   g_srcs[NE];
__device__ int   g_is_i32;   // 1 if edge_index is int32, 0 if int64

struct GemmParams {
    const float* W[4];
    const float* b[4];
};

// ---------------------------------------------------------------------------
// Dtype detection: if edge_index is int64 (values < 2^31), every odd 32-bit
// word is 0. If int32, odd words hold edge ids (rarely 0). Scan 4096 odd
// words; any nonzero => int32.
// ---------------------------------------------------------------------------
__global__ void detect_kernel(const int* __restrict__ ei32) {
    __shared__ int found;
    if (threadIdx.x == 0) found = 0;
    __syncthreads();
    for (int i = threadIdx.x; i < 4096; i += blockDim.x) {
        if (ei32[2 * i + 1] != 0) found = 1;
    }
    __syncthreads();
    if (threadIdx.x == 0) g_is_i32 = found;
}

__device__ __forceinline__ int load_src(const void* ei, int e) {
    if (g_is_i32) return ((const int*)ei)[e];
    return (int)((const long long*)ei)[e];
}
__device__ __forceinline__ int load_dst(const void* ei, int e) {
    if (g_is_i32) return ((const int*)ei)[NE + e];
    return (int)((const long long*)ei)[NE + e];
}

// ---------------------------------------------------------------------------
// CSR build
// ---------------------------------------------------------------------------
__global__ void deg_zero_kernel() {
    int i = blockIdx.x * blockDim.x + threadIdx.x;
    if (i < NN) g_deg[i] = 0;
}

__global__ void hist_kernel(const void* __restrict__ ei) {
    int e = blockIdx.x * blockDim.x + threadIdx.x;
    if (e >= NE) return;
    int d = load_dst(ei, e);
    int s = load_src(ei, e);
    if ((unsigned)d < NN && (unsigned)s < NN) atomicAdd(&g_deg[d], 1);
}

__global__ __launch_bounds__(CHUNK) void scan1_kernel() {
    __shared__ int sh[CHUNK];
    int base = blockIdx.x * CHUNK;
    int t = threadIdx.x;
    int i = base + t;
    int v = (i < NN) ? g_deg[i] : 0;
    sh[t] = v;
    __syncthreads();
#pragma unroll
    for (int off = 1; off < CHUNK; off <<= 1) {
        int add = (t >= off) ? sh[t - off] : 0;
        __syncthreads();
        sh[t] += add;
        __syncthreads();
    }
    if (i < NN) g_rptmp[i + 1] = sh[t];
    if (t == CHUNK - 1) g_blocksums[blockIdx.x] = sh[t];
}

__global__ __launch_bounds__(128) void scan2_kernel() {
    __shared__ int sh[128];
    int t = threadIdx.x;
    int v = (t < NBLK) ? g_blocksums[t] : 0;
    sh[t] = v;
    __syncthreads();
#pragma unroll
    for (int off = 1; off < 128; off <<= 1) {
        int add = (t >= off) ? sh[t - off] : 0;
        __syncthreads();
        sh[t] += add;
        __syncthreads();
    }
    if (t < NBLK) g_blockoffs[t] = sh[t] - v;  // exclusive
}

__global__ void scan3_kernel() {
    int i = blockIdx.x * blockDim.x + threadIdx.x;
    if (i >= NN) return;
    g_rowptr[i + 1] = g_rptmp[i + 1] + g_blockoffs[i >> 10];
    g_wpos[i] = (i == 0) ? 0 : g_rptmp[i] + g_blockoffs[(i - 1) >> 10];
    if (i == 0) g_rowptr[0] = 0;
}

__global__ void scatter_kernel(const void* __restrict__ ei) {
    int e = blockIdx.x * blockDim.x + threadIdx.x;
    if (e >= NE) return;
    int d = load_dst(ei, e);
    int s = load_src(ei, e);
    if ((unsigned)d >= NN || (unsigned)s >= NN) return;
    int pos = atomicAdd(&g_wpos[d], 1);
    g_srcs[pos] = s;
}

// ---------------------------------------------------------------------------
// Fused 4-way SGEMM: {g_q,g_k,g_v,g_s}[m] = X @ W_m + b_m
// BM=128, BN=128, BK=16, 256 threads, 8x8 per thread. blockIdx.y = matrix.
// ---------------------------------------------------------------------------
__global__ __launch_bounds__(256) void gemm4_kernel(const float* __restrict__ Xin,
                                                    GemmParams p, int use_h) {
    const int mat = blockIdx.y;
    const float* __restrict__ X = use_h ? g_h : Xin;
    const float* __restrict__ W = p.W[mat];
    const float* __restrict__ bias = p.b[mat];
    float* outs[4] = {g_q, g_k, g_v, g_s};
    float* __restrict__ Y = outs[mat];

    __shared__ float Xs[16][128];  // [k][row]
    __shared__ float Ws[16][128];  // [k][col]

    const int tid = threadIdx.x;
    const int tx = tid & 15;
    const int ty = tid >> 4;
    const int blockRow = blockIdx.x * 128;

    const int lr = tid >> 1;
    const int lc = (tid & 1) * 8;
    const int wr = tid >> 4;
    const int wc = (tid & 15) * 8;

    float acc[8][8];
#pragma unroll
    for (int i = 0; i < 8; i++)
#pragma unroll
        for (int j = 0; j < 8; j++) acc[i][j] = 0.0f;

    for (int k0 = 0; k0 < 128; k0 += 16) {
        int gr = blockRow + lr;
        float4 xa, xb;
        if (gr < NN) {
            xa = *(const float4*)&X[gr * 128 + k0 + lc];
            xb = *(const float4*)&X[gr * 128 + k0 + lc + 4];
        } else {
            xa = make_float4(0.f, 0.f, 0.f, 0.f);
            xb = xa;
        }
        Xs[lc + 0][lr] = xa.x; Xs[lc + 1][lr] = xa.y;
        Xs[lc + 2][lr] = xa.z; Xs[lc + 3][lr] = xa.w;
        Xs[lc + 4][lr] = xb.x; Xs[lc + 5][lr] = xb.y;
        Xs[lc + 6][lr] = xb.z; Xs[lc + 7][lr] = xb.w;

        float4 wa = *(const float4*)&W[(k0 + wr) * 128 + wc];
        float4 wb = *(const float4*)&W[(k0 + wr) * 128 + wc + 4];
        *(float4*)&Ws[wr][wc] = wa;
        *(float4*)&Ws[wr][wc + 4] = wb;

        __syncthreads();

#pragma unroll
        for (int kk = 0; kk < 16; kk++) {
            float4 a0 = *(float4*)&Xs[kk][ty * 8];
            float4 a1 = *(float4*)&Xs[kk][ty * 8 + 4];
            float4 b0 = *(float4*)&Ws[kk][tx * 8];
            float4 b1 = *(float4*)&Ws[kk][tx * 8 + 4];
            float a[8] = {a0.x, a0.y, a0.z, a0.w, a1.x, a1.y, a1.z, a1.w};
            float b[8] = {b0.x, b0.y, b0.z, b0.w, b1.x, b1.y, b1.z, b1.w};
#pragma unroll
            for (int i = 0; i < 8; i++)
#pragma unroll
                for (int j = 0; j < 8; j++) acc[i][j] = fmaf(a[i], b[j], acc[i][j]);
        }
        __syncthreads();
    }

    float bl[8];
#pragma unroll
    for (int j = 0; j < 8; j++) bl[j] = bias[tx * 8 + j];

#pragma unroll
    for (int i = 0; i < 8; i++) {
        int row = blockRow + ty * 8 + i;
        if (row < NN) {
#pragma unroll
            for (int j = 0; j < 8; j += 4) {
                float4 r;
                r.x = acc[i][j + 0] + bl[j + 0];
                r.y = acc[i][j + 1] + bl[j + 1];
                r.z = acc[i][j + 2] + bl[j + 2];
                r.w = acc[i][j + 3] + bl[j + 3];
                *(float4*)&Y[row * 128 + tx * 8 + j] = r;
            }
        }
    }
}

// ---------------------------------------------------------------------------
// Fused attention: one warp per dst node; register accumulation, no atomics.
// ---------------------------------------------------------------------------
__global__ __launch_bounds__(256) void attn_kernel(float* __restrict__ outp,
                                                   int relu, int write_h) {
    const int node = (blockIdx.x * blockDim.x + threadIdx.x) >> 5;
    const int lane = threadIdx.x & 31;
    if (node >= NN) return;

    float* __restrict__ out = write_h ? g_h : outp;

    const int beg = g_rowptr[node];
    const int end = g_rowptr[node + 1];

    const float4 q4 = ((const float4*)&g_q[node * C])[lane];

    float ax = 0.f, ay = 0.f, az = 0.f, aw = 0.f;
    float esum = 0.f;

    for (int idx = beg; idx < end; idx++) {
        const int src = g_srcs[idx];
        const float4 k4 = ((const float4*)&g_k[src * C])[lane];
        float p = q4.x * k4.x + q4.y * k4.y + q4.z * k4.z + q4.w * k4.w;
#pragma unroll
        for (int o = 16; o > 0; o >>= 1) p += __shfl_xor_sync(0xFFFFFFFFu, p, o);
        const float w = __expf(p * 0.08838834764831845f);  // 1/sqrt(128)
        esum += w;
        const float4 v4 = ((const float4*)&g_v[src * C])[lane];
        ax = fmaf(w, v4.x, ax);
        ay = fmaf(w, v4.y, ay);
        az = fmaf(w, v4.z, az);
        aw = fmaf(w, v4.w, aw);
    }

    const float inv = (esum > 0.0f) ? (1.0f / esum) : 0.0f;
    const float4 s4 = ((const float4*)&g_s[node * C])[lane];
    float4 r;
    r.x = fmaf(ax, inv, s4.x);
    r.y = fmaf(ay, inv, s4.y);
    r.z = fmaf(az, inv, s4.z);
    r.w = fmaf(aw, inv, s4.w);
    if (relu) {
        r.x = fmaxf(r.x, 0.0f);
        r.y = fmaxf(r.y, 0.0f);
        r.z = fmaxf(r.z, 0.0f);
        r.w = fmaxf(r.w, 0.0f);
    }
    *(float4*)&out[node * C + lane * 4] = r;
}

// ---------------------------------------------------------------------------
// Launch (pure kernel launches — graph-capture safe)
// ---------------------------------------------------------------------------
extern "C" void kernel_launch(void* const* d_in, const int* in_sizes, int n_in,
                              void* d_out, int out_size) {
    const float* x = (const float*)d_in[0];
    const void* ei = d_in[1];

    GemmParams p1, p2;
    p1.W[0] = (const float*)d_in[2];  p1.b[0] = (const float*)d_in[3];
    p1.W[1] = (const float*)d_in[4];  p1.b[1] = (const float*)d_in[5];
    p1.W[2] = (const float*)d_in[6];  p1.b[2] = (const float*)d_in[7];
    p1.W[3] = (const float*)d_in[8];  p1.b[3] = (const float*)d_in[9];

    p2.W[0] = (const float*)d_in[10]; p2.b[0] = (const float*)d_in[11];
    p2.W[1] = (const float*)d_in[12]; p2.b[1] = (const float*)d_in[13];
    p2.W[2] = (const float*)d_in[14]; p2.b[2] = (const float*)d_in[15];
    p2.W[3] = (const float*)d_in[16]; p2.b[3] = (const float*)d_in[17];

    const int node_grid = (NN + 255) / 256;
    const int edge_grid = (NE + 255) / 256;
    const dim3 gemm_grid((NN + 127) / 128, 4);
    const int attn_grid = (NN * 32 + 255) / 256;

    // ---- dtype detection + CSR build ----
    detect_kernel<<<1, 256>>>((const int*)ei);
    deg_zero_kernel<<<node_grid, 256>>>();
    hist_kernel<<<edge_grid, 256>>>(ei);
    scan1_kernel<<<NBLK, CHUNK>>>();
    scan2_kernel<<<1, 128>>>();
    scan3_kernel<<<node_grid, 256>>>();
    scatter_kernel<<<edge_grid, 256>>>(ei);

    // ---- layer 1 ----
    gemm4_kernel<<<gemm_grid, 256>>>(x, p1, 0);
    attn_kernel<<<attn_grid, 256>>>(nullptr, 1, 1);

    // ---- layer 2 ----
    gemm4_kernel<<<gemm_grid, 256>>>(nullptr, p2, 1);
    attn_kernel<<<attn_grid, 256>>>((float*)d_out, 0, 0);
}

// round 6
// speedup vs baseline: 1.6979x; 1.6979x over previous
#include <cuda_runtime.h>

// ---------------------------------------------------------------------------
// TemporalGNN: 2x TransformerConv(heads=1), N=100k nodes, E=800k edges, C=128.
// CSR-by-dst build + per-layer [tf32 tensor-core gemm4] -> [fused attention].
//
// NOTE: resubmission of the Round-5 kernel verbatim — that round died to a
// container-infra failure ("GB300 container failed twice", same as Round 0
// with the stub), so the tf32 theory is untested, not falsified.
// ---------------------------------------------------------------------------

#define NN 100000
#define NE 800000
#define C  128
#define CHUNK 1024
#define NBLK ((NN + CHUNK - 1) / CHUNK)  // 98

__device__ float    g_q[NN * C];
__device__ float    g_k[NN * C];
__device__ float    g_v[NN * C];
__device__ float    g_s[NN * C];
__device__ float    g_h[NN * C];
__device__ unsigned g_wt[8 * C * C];   // all 8 weight mats, transposed, tf32 bits
__device__ int      g_deg[NN];
__device__ int      g_rptmp[NN + 1];
__device__ int      g_rowptr[NN + 1];
__device__ int      g_wpos[NN];
__device__ int      g_blocksums[NBLK];
__device__ int      g_blockoffs[NBLK];
__device__ int      g_srcs[NE];
__device__ int      g_is_i32;

struct WPtrs  { const float* W[8]; };
struct BiasPtrs { const float* b[4]; };

__device__ __forceinline__ unsigned f2tf32(float x) {
    unsigned u;
    asm("cvt.rna.tf32.f32 %0, %1;" : "=r"(u) : "f"(x));
    return u;
}

__device__ __forceinline__ void mma_tf32(float* c, const unsigned* a, const unsigned* b) {
    asm volatile(
        "mma.sync.aligned.m16n8k8.row.col.f32.tf32.tf32.f32 "
        "{%0,%1,%2,%3}, {%4,%5,%6,%7}, {%8,%9}, {%0,%1,%2,%3};"
        : "+f"(c[0]), "+f"(c[1]), "+f"(c[2]), "+f"(c[3])
        : "r"(a[0]), "r"(a[1]), "r"(a[2]), "r"(a[3]), "r"(b[0]), "r"(b[1]));
}

// ---------------------------------------------------------------------------
// edge_index dtype detection (int32 vs int64): int64 values < 2^31 have all
// odd 32-bit words zero.
// ---------------------------------------------------------------------------
__global__ void detect_kernel(const int* __restrict__ ei32) {
    __shared__ int found;
    if (threadIdx.x == 0) found = 0;
    __syncthreads();
    for (int i = threadIdx.x; i < 4096; i += blockDim.x)
        if (ei32[2 * i + 1] != 0) found = 1;
    __syncthreads();
    if (threadIdx.x == 0) g_is_i32 = found;
}

__device__ __forceinline__ int load_src(const void* ei, int e) {
    if (g_is_i32) return ((const int*)ei)[e];
    return (int)((const long long*)ei)[e];
}
__device__ __forceinline__ int load_dst(const void* ei, int e) {
    if (g_is_i32) return ((const int*)ei)[NE + e];
    return (int)((const long long*)ei)[NE + e];
}

// ---------------------------------------------------------------------------
// CSR build
// ---------------------------------------------------------------------------
__global__ void deg_zero_kernel() {
    int i = blockIdx.x * blockDim.x + threadIdx.x;
    if (i < NN) g_deg[i] = 0;
}

__global__ void hist_kernel(const void* __restrict__ ei) {
    int e = blockIdx.x * blockDim.x + threadIdx.x;
    if (e >= NE) return;
    int d = load_dst(ei, e);
    int s = load_src(ei, e);
    if ((unsigned)d < NN && (unsigned)s < NN) atomicAdd(&g_deg[d], 1);
}

__global__ __launch_bounds__(CHUNK) void scan1_kernel() {
    __shared__ int sh[CHUNK];
    int t = threadIdx.x;
    int i = blockIdx.x * CHUNK + t;
    int v = (i < NN) ? g_deg[i] : 0;
    sh[t] = v;
    __syncthreads();
#pragma unroll
    for (int off = 1; off < CHUNK; off <<= 1) {
        int add = (t >= off) ? sh[t - off] : 0;
        __syncthreads();
        sh[t] += add;
        __syncthreads();
    }
    if (i < NN) g_rptmp[i + 1] = sh[t];
    if (t == CHUNK - 1) g_blocksums[blockIdx.x] = sh[t];
}

__global__ __launch_bounds__(128) void scan2_kernel() {
    __shared__ int sh[128];
    int t = threadIdx.x;
    int v = (t < NBLK) ? g_blocksums[t] : 0;
    sh[t] = v;
    __syncthreads();
#pragma unroll
    for (int off = 1; off < 128; off <<= 1) {
        int add = (t >= off) ? sh[t - off] : 0;
        __syncthreads();
        sh[t] += add;
        __syncthreads();
    }
    if (t < NBLK) g_blockoffs[t] = sh[t] - v;
}

__global__ void scan3_kernel() {
    int i = blockIdx.x * blockDim.x + threadIdx.x;
    if (i >= NN) return;
    g_rowptr[i + 1] = g_rptmp[i + 1] + g_blockoffs[i >> 10];
    g_wpos[i] = (i == 0) ? 0 : g_rptmp[i] + g_blockoffs[(i - 1) >> 10];
    if (i == 0) g_rowptr[0] = 0;
}

__global__ void scatter_kernel(const void* __restrict__ ei) {
    int e = blockIdx.x * blockDim.x + threadIdx.x;
    if (e >= NE) return;
    int d = load_dst(ei, e);
    int s = load_src(ei, e);
    if ((unsigned)d >= NN || (unsigned)s >= NN) return;
    int pos = atomicAdd(&g_wpos[d], 1);
    g_srcs[pos] = s;
}

// ---------------------------------------------------------------------------
// Weight prep: transpose W[k][n] -> Wt[n][k] with round-to-nearest tf32.
// blockIdx.y = matrix index (0..7).
// ---------------------------------------------------------------------------
__global__ void wprep_kernel(WPtrs wp) {
    int mat = blockIdx.y;
    int idx = blockIdx.x * blockDim.x + threadIdx.x;
    if (idx >= C * C) return;
    int k = idx >> 7;
    int n = idx & 127;
    g_wt[mat * C * C + n * C + k] = f2tf32(wp.W[mat][idx]);
}

// ---------------------------------------------------------------------------
// tf32 tensor-core GEMM: {g_q,g_k,g_v,g_s}[mat] = X @ W_mat + b_mat
// BM=128, BN=128, BK=32. 256 threads = 8 warps, warp tile 64x32
// (4x4 frags of m16n8k8). Smem padded [128][36] => conflict-free frag LDS.
// ---------------------------------------------------------------------------
__global__ __launch_bounds__(256) void gemm4_tc(const float* __restrict__ Xin,
                                                BiasPtrs bp, int use_h, int wt_base) {
    const int mat = blockIdx.y;
    const float* __restrict__ X = use_h ? g_h : Xin;
    const float* __restrict__ bias = bp.b[mat];
    float* outs[4] = {g_q, g_k, g_v, g_s};
    float* __restrict__ Y = outs[mat];
    const unsigned* __restrict__ Wt = &g_wt[(wt_base + mat) * C * C];

    __shared__ unsigned Xs[128][36];
    __shared__ unsigned Ws[128][36];

    const int tid = threadIdx.x;
    const int lane = tid & 31;
    const int wid = tid >> 5;
    const int warp_m = (wid & 1) * 64;
    const int warp_n = (wid >> 1) * 32;
    const int blockRow = blockIdx.x * 128;

    const int lrow = tid >> 1;           // 0..127
    const int lcol = (tid & 1) * 16;     // 0 or 16

    float acc[4][4][4];
#pragma unroll
    for (int mi = 0; mi < 4; mi++)
#pragma unroll
        for (int ni = 0; ni < 4; ni++)
#pragma unroll
            for (int r = 0; r < 4; r++) acc[mi][ni][r] = 0.0f;

    for (int k0 = 0; k0 < 128; k0 += 32) {
        const int gr = blockRow + lrow;
#pragma unroll
        for (int j = 0; j < 4; j++) {
            const int c = lcol + j * 4;
            float4 xv = make_float4(0.f, 0.f, 0.f, 0.f);
            if (gr < NN) xv = *(const float4*)&X[gr * 128 + k0 + c];
            uint4 uv;
            uv.x = f2tf32(xv.x); uv.y = f2tf32(xv.y);
            uv.z = f2tf32(xv.z); uv.w = f2tf32(xv.w);
            *(uint4*)&Xs[lrow][c] = uv;
            *(uint4*)&Ws[lrow][c] = *(const uint4*)&Wt[lrow * 128 + k0 + c];
        }
        __syncthreads();

#pragma unroll
        for (int kk = 0; kk < 32; kk += 8) {
            unsigned a[4][4], b[4][2];
#pragma unroll
            for (int mi = 0; mi < 4; mi++) {
                const int r = warp_m + mi * 16 + (lane >> 2);
                const int kc = kk + (lane & 3);
                a[mi][0] = Xs[r][kc];
                a[mi][1] = Xs[r + 8][kc];
                a[mi][2] = Xs[r][kc + 4];
                a[mi][3] = Xs[r + 8][kc + 4];
            }
#pragma unroll
            for (int ni = 0; ni < 4; ni++) {
                const int n = warp_n + ni * 8 + (lane >> 2);
                const int kc = kk + (lane & 3);
                b[ni][0] = Ws[n][kc];
                b[ni][1] = Ws[n][kc + 4];
            }
#pragma unroll
            for (int mi = 0; mi < 4; mi++)
#pragma unroll
                for (int ni = 0; ni < 4; ni++) mma_tf32(acc[mi][ni], a[mi], b[ni]);
        }
        __syncthreads();
    }

    // Epilogue: C frag layout c0/c1 row=lane>>2 cols 2*(lane&3),+1; c2/c3 row+8.
    float2 b2[4];
#pragma unroll
    for (int ni = 0; ni < 4; ni++)
        b2[ni] = *(const float2*)&bias[warp_n + ni * 8 + (lane & 3) * 2];

#pragma unroll
    for (int mi = 0; mi < 4; mi++) {
        const int row0 = blockRow + warp_m + mi * 16 + (lane >> 2);
        const int row1 = row0 + 8;
#pragma unroll
        for (int ni = 0; ni < 4; ni++) {
            const int col = warp_n + ni * 8 + (lane & 3) * 2;
            if (row0 < NN) {
                float2 r;
                r.x = acc[mi][ni][0] + b2[ni].x;
                r.y = acc[mi][ni][1] + b2[ni].y;
                *(float2*)&Y[row0 * 128 + col] = r;
            }
            if (row1 < NN) {
                float2 r;
                r.x = acc[mi][ni][2] + b2[ni].x;
                r.y = acc[mi][ni][3] + b2[ni].y;
                *(float2*)&Y[row1 * 128 + col] = r;
            }
        }
    }
}

// ---------------------------------------------------------------------------
// Fused attention: one warp per dst node; register accumulation, no atomics.
// ---------------------------------------------------------------------------
__global__ __launch_bounds__(256) void attn_kernel(float* __restrict__ outp,
                                                   int relu, int write_h) {
    const int node = (blockIdx.x * blockDim.x + threadIdx.x) >> 5;
    const int lane = threadIdx.x & 31;
    if (node >= NN) return;

    float* __restrict__ out = write_h ? g_h : outp;

    const int beg = g_rowptr[node];
    const int end = g_rowptr[node + 1];

    const float4 q4 = ((const float4*)&g_q[node * C])[lane];

    float ax = 0.f, ay = 0.f, az = 0.f, aw = 0.f;
    float esum = 0.f;

    for (int idx = beg; idx < end; idx++) {
        const int src = g_srcs[idx];
        const float4 k4 = ((const float4*)&g_k[src * C])[lane];
        float p = q4.x * k4.x + q4.y * k4.y + q4.z * k4.z + q4.w * k4.w;
#pragma unroll
        for (int o = 16; o > 0; o >>= 1) p += __shfl_xor_sync(0xFFFFFFFFu, p, o);
        const float w = __expf(p * 0.08838834764831845f);  // 1/sqrt(128)
        esum += w;
        const float4 v4 = ((const float4*)&g_v[src * C])[lane];
        ax = fmaf(w, v4.x, ax);
        ay = fmaf(w, v4.y, ay);
        az = fmaf(w, v4.z, az);
        aw = fmaf(w, v4.w, aw);
    }

    const float inv = (esum > 0.0f) ? (1.0f / esum) : 0.0f;
    const float4 s4 = ((const float4*)&g_s[node * C])[lane];
    float4 r;
    r.x = fmaf(ax, inv, s4.x);
    r.y = fmaf(ay, inv, s4.y);
    r.z = fmaf(az, inv, s4.z);
    r.w = fmaf(aw, inv, s4.w);
    if (relu) {
        r.x = fmaxf(r.x, 0.0f);
        r.y = fmaxf(r.y, 0.0f);
        r.z = fmaxf(r.z, 0.0f);
        r.w = fmaxf(r.w, 0.0f);
    }
    *(float4*)&out[node * C + lane * 4] = r;
}

// ---------------------------------------------------------------------------
// Launch (pure kernel launches — graph-capture safe)
// ---------------------------------------------------------------------------
extern "C" void kernel_launch(void* const* d_in, const int* in_sizes, int n_in,
                              void* d_out, int out_size) {
    const float* x = (const float*)d_in[0];
    const void* ei = d_in[1];

    WPtrs wp;
    wp.W[0] = (const float*)d_in[2];  wp.W[1] = (const float*)d_in[4];
    wp.W[2] = (const float*)d_in[6];  wp.W[3] = (const float*)d_in[8];
    wp.W[4] = (const float*)d_in[10]; wp.W[5] = (const float*)d_in[12];
    wp.W[6] = (const float*)d_in[14]; wp.W[7] = (const float*)d_in[16];

    BiasPtrs b1, b2;
    b1.b[0] = (const float*)d_in[3];  b1.b[1] = (const float*)d_in[5];
    b1.b[2] = (const float*)d_in[7];  b1.b[3] = (const float*)d_in[9];
    b2.b[0] = (const float*)d_in[11]; b2.b[1] = (const float*)d_in[13];
    b2.b[2] = (const float*)d_in[15]; b2.b[3] = (const float*)d_in[17];

    const int node_grid = (NN + 255) / 256;
    const int edge_grid = (NE + 255) / 256;
    const dim3 gemm_grid((NN + 127) / 128, 4);
    const dim3 wprep_grid((C * C + 255) / 256, 8);
    const int attn_grid = (NN * 32 + 255) / 256;

    // ---- prep: dtype detect, weight transpose/convert, CSR build ----
    detect_kernel<<<1, 256>>>((const int*)ei);
    wprep_kernel<<<wprep_grid, 256>>>(wp);
    deg_zero_kernel<<<node_grid, 256>>>();
    hist_kernel<<<edge_grid, 256>>>(ei);
    scan1_kernel<<<NBLK, CHUNK>>>();
    scan2_kernel<<<1, 128>>>();
    scan3_kernel<<<node_grid, 256>>>();
    scatter_kernel<<<edge_grid, 256>>>(ei);

    // ---- layer 1 ----
    gemm4_tc<<<gemm_grid, 256>>>(x, b1, 0, 0);
    attn_kernel<<<attn_grid, 256>>>(nullptr, 1, 1);

    // ---- layer 2 ----
    gemm4_tc<<<gemm_grid, 256>>>(nullptr, b2, 1, 4);
    attn_kernel<<<attn_grid, 256>>>((float*)d_out, 0, 0);
}